// round 1
// baseline (speedup 1.0000x reference)
#include <cuda_runtime.h>
#include <math.h>

// Problem constants
#define BB 2048          // batch
#define NN 4096          // 2*B rows of z
#define DD 512           // half feature dim
#define NHALF 12         // 6 inputs x 2 halves
#define NLOSS 9          // contrastive losses
#define NORTHO 12        // ortho pairs
#define TINV 5.0f        // 1/temperature

// Scratch (device globals; no allocation allowed)
__device__ float g_zn[NHALF * BB * DD];     // normalized halves: ~50.3 MB
__device__ float g_rowsum[NLOSS * NN];      // per-row sum of exp(sim/T), self excluded

// half index h = (view*3 + modality)*2 + part   (part 0 = shared, 1 = private)
// contrastive pairs (A,B):
__constant__ int c_cpA[NLOSS] = {0, 0, 2, 6, 6,  8, 1, 3, 5};
__constant__ int c_cpB[NLOSS] = {2, 4, 4, 8, 10, 10, 7, 9, 11};
// ortho pairs:
__constant__ int c_opA[NORTHO] = {0, 2, 4, 1, 1, 3, 6, 8, 10, 7, 7, 9};
__constant__ int c_opB[NORTHO] = {1, 3, 5, 3, 5, 5, 7, 9, 11, 9, 11, 11};

// ---------------------------------------------------------------------------
// 0) zero rowsums + output scalar (graph replays need re-init every launch)
// ---------------------------------------------------------------------------
__global__ void zero_kernel(float* out) {
    int i = blockIdx.x * blockDim.x + threadIdx.x;
    if (i < NLOSS * NN) g_rowsum[i] = 0.0f;
    if (i == 0) out[0] = 0.0f;
}

// ---------------------------------------------------------------------------
// 1) row-normalize all 12 halves into g_zn.  One warp per row.
// ---------------------------------------------------------------------------
__global__ void norm_kernel(const float* __restrict__ i0, const float* __restrict__ i1,
                            const float* __restrict__ i2, const float* __restrict__ i3,
                            const float* __restrict__ i4, const float* __restrict__ i5) {
    int gw   = (blockIdx.x * blockDim.x + threadIdx.x) >> 5;
    int lane = threadIdx.x & 31;
    if (gw >= NHALF * BB) return;
    int h = gw / BB;
    int r = gw % BB;
    int m = h >> 1;
    const float* base = (m == 0) ? i0 : (m == 1) ? i1 : (m == 2) ? i2
                       : (m == 3) ? i3 : (m == 4) ? i4 : i5;
    const float* src = base + (size_t)r * 1024 + (size_t)(h & 1) * 512;

    float4 v[4];
    float ss = 0.0f;
#pragma unroll
    for (int w = 0; w < 4; w++) {
        v[w] = reinterpret_cast<const float4*>(src)[lane + w * 32];
        ss += v[w].x * v[w].x + v[w].y * v[w].y + v[w].z * v[w].z + v[w].w * v[w].w;
    }
#pragma unroll
    for (int o = 16; o; o >>= 1) ss += __shfl_xor_sync(0xFFFFFFFFu, ss, o);
    float inv = 1.0f / fmaxf(sqrtf(ss), 1e-8f);

    float* dst = g_zn + (size_t)h * BB * DD + (size_t)r * DD;
#pragma unroll
    for (int w = 0; w < 4; w++) {
        float4 o4;
        o4.x = v[w].x * inv; o4.y = v[w].y * inv;
        o4.z = v[w].z * inv; o4.w = v[w].w * inv;
        reinterpret_cast<float4*>(dst)[lane + w * 32] = o4;
    }
}

// ---------------------------------------------------------------------------
// 2) symmetric tiled sim + exp accumulation.
//    Grid: x = 528 upper-triangle 128x128 tiles, y = loss index.
//    256 threads (16x16), 8x8 register tile each.
// ---------------------------------------------------------------------------
__global__ __launch_bounds__(256, 2) void ctile_kernel() {
    const int loss = blockIdx.y;
    int t  = blockIdx.x;
    int bi = 0;
    while (t >= 32 - bi) { t -= 32 - bi; bi++; }
    const int bj = bi + t;

    const float* __restrict__ ZA = g_zn + (size_t)c_cpA[loss] * BB * DD;
    const float* __restrict__ ZB = g_zn + (size_t)c_cpB[loss] * BB * DD;

    __shared__ float As[16][132];
    __shared__ float Bs[16][132];
    __shared__ float colbuf[128];

    const int tid = threadIdx.x;
    const int tx  = tid & 15;
    const int ty  = tid >> 4;

    float acc[8][8];
#pragma unroll
    for (int i = 0; i < 8; i++)
#pragma unroll
        for (int j = 0; j < 8; j++) acc[i][j] = 0.0f;

    const int r0 = bi * 128;
    const int c0 = bj * 128;

    for (int kc = 0; kc < DD; kc += 16) {
#pragma unroll
        for (int it = 0; it < 2; it++) {
            int idx = it * 256 + tid;
            int r   = idx >> 2;           // 0..127
            int kq  = (idx & 3) * 4;
            int grA = r0 + r;
            const float* pA = (grA < BB ? ZA + (size_t)grA * DD
                                        : ZB + (size_t)(grA - BB) * DD) + kc + kq;
            float4 a = *reinterpret_cast<const float4*>(pA);
            As[kq + 0][r] = a.x; As[kq + 1][r] = a.y;
            As[kq + 2][r] = a.z; As[kq + 3][r] = a.w;
            int grB = c0 + r;
            const float* pB = (grB < BB ? ZA + (size_t)grB * DD
                                        : ZB + (size_t)(grB - BB) * DD) + kc + kq;
            float4 b = *reinterpret_cast<const float4*>(pB);
            Bs[kq + 0][r] = b.x; Bs[kq + 1][r] = b.y;
            Bs[kq + 2][r] = b.z; Bs[kq + 3][r] = b.w;
        }
        __syncthreads();
#pragma unroll
        for (int k = 0; k < 16; k++) {
            float af[8], bf[8];
            *reinterpret_cast<float4*>(&af[0]) = *reinterpret_cast<const float4*>(&As[k][ty * 8]);
            *reinterpret_cast<float4*>(&af[4]) = *reinterpret_cast<const float4*>(&As[k][ty * 8 + 4]);
            *reinterpret_cast<float4*>(&bf[0]) = *reinterpret_cast<const float4*>(&Bs[k][tx * 8]);
            *reinterpret_cast<float4*>(&bf[4]) = *reinterpret_cast<const float4*>(&Bs[k][tx * 8 + 4]);
#pragma unroll
            for (int ii = 0; ii < 8; ii++)
#pragma unroll
                for (int jj = 0; jj < 8; jj++)
                    acc[ii][jj] += af[ii] * bf[jj];
        }
        __syncthreads();
    }

    // epilogue: exp + row/col partial sums
    const bool diag = (bi == bj);
    float rsum[8], csum[8];
#pragma unroll
    for (int i = 0; i < 8; i++) { rsum[i] = 0.0f; csum[i] = 0.0f; }

#pragma unroll
    for (int ii = 0; ii < 8; ii++) {
        int R = r0 + ty * 8 + ii;
#pragma unroll
        for (int jj = 0; jj < 8; jj++) {
            int C = c0 + tx * 8 + jj;
            float e = (diag && R == C) ? 0.0f : __expf(acc[ii][jj] * TINV);
            rsum[ii] += e;
            csum[jj] += e;
        }
    }

    // row sums: reduce across the 16 tx threads (contiguous 16-lane segments)
#pragma unroll
    for (int ii = 0; ii < 8; ii++) {
        float v = rsum[ii];
#pragma unroll
        for (int o = 8; o; o >>= 1) v += __shfl_xor_sync(0xFFFFFFFFu, v, o);
        if (tx == 0) atomicAdd(&g_rowsum[loss * NN + r0 + ty * 8 + ii], v);
    }

    // col sums (transpose contribution) only for off-diagonal tiles
    if (!diag) {
        if (tid < 128) colbuf[tid] = 0.0f;
        __syncthreads();
#pragma unroll
        for (int jj = 0; jj < 8; jj++) atomicAdd(&colbuf[tx * 8 + jj], csum[jj]);
        __syncthreads();
        if (tid < 128) atomicAdd(&g_rowsum[loss * NN + c0 + tid], colbuf[tid]);
    }
}

// ---------------------------------------------------------------------------
// 3) ortho losses: mean(1 - cos) over normalized halves. One warp per (pair,row).
// ---------------------------------------------------------------------------
__global__ void ortho_kernel(float* out) {
    int gw   = (blockIdx.x * blockDim.x + threadIdx.x) >> 5;
    int lane = threadIdx.x & 31;
    __shared__ float red[8];
    float c = 0.0f;
    if (gw < NORTHO * BB) {
        int p = gw / BB;
        int r = gw % BB;
        const float* a = g_zn + (size_t)c_opA[p] * BB * DD + (size_t)r * DD;
        const float* b = g_zn + (size_t)c_opB[p] * BB * DD + (size_t)r * DD;
        float d = 0.0f;
#pragma unroll
        for (int w = 0; w < 4; w++) {
            float4 x = reinterpret_cast<const float4*>(a)[lane + w * 32];
            float4 y = reinterpret_cast<const float4*>(b)[lane + w * 32];
            d += x.x * y.x + x.y * y.y + x.z * y.z + x.w * y.w;
        }
#pragma unroll
        for (int o = 16; o; o >>= 1) d += __shfl_xor_sync(0xFFFFFFFFu, d, o);
        if (lane == 0) c = (1.0f - d) * (1.0f / (float)BB);
    }
#pragma unroll
    for (int o = 16; o; o >>= 1) c += __shfl_xor_sync(0xFFFFFFFFu, c, o);
    if (lane == 0) red[threadIdx.x >> 5] = c;
    __syncthreads();
    if (threadIdx.x < 8) {
        float v = red[threadIdx.x];
#pragma unroll
        for (int o = 4; o; o >>= 1) v += __shfl_xor_sync(0xFFu, v, o);
        if (threadIdx.x == 0) atomicAdd(out, v);
    }
}

// ---------------------------------------------------------------------------
// 4) finalize contrastive: per row, log(rowsum) and exact pos dot.
//    One warp per (loss, row).
// ---------------------------------------------------------------------------
__global__ void finalize_kernel(float* out) {
    int gw   = (blockIdx.x * blockDim.x + threadIdx.x) >> 5;
    int lane = threadIdx.x & 31;
    __shared__ float red[8];
    float c = 0.0f;
    if (gw < NLOSS * NN) {
        int loss = gw / NN;
        int i    = gw % NN;
        float val = logf(g_rowsum[loss * NN + i]);
        if (i < BB) {
            const float* a = g_zn + (size_t)c_cpA[loss] * BB * DD + (size_t)i * DD;
            const float* b = g_zn + (size_t)c_cpB[loss] * BB * DD + (size_t)i * DD;
            float d = 0.0f;
#pragma unroll
            for (int w = 0; w < 4; w++) {
                float4 x = reinterpret_cast<const float4*>(a)[lane + w * 32];
                float4 y = reinterpret_cast<const float4*>(b)[lane + w * 32];
                d += x.x * y.x + x.y * y.y + x.z * y.z + x.w * y.w;
            }
#pragma unroll
            for (int o = 16; o; o >>= 1) d += __shfl_xor_sync(0xFFFFFFFFu, d, o);
            // pos_i == pos_{i+B}: subtract both contributions here
            val -= 2.0f * d * TINV;
        }
        if (lane == 0) c = val * (1.0f / (float)NN);
    }
#pragma unroll
    for (int o = 16; o; o >>= 1) c += __shfl_xor_sync(0xFFFFFFFFu, c, o);
    if (lane == 0) red[threadIdx.x >> 5] = c;
    __syncthreads();
    if (threadIdx.x < 8) {
        float v = red[threadIdx.x];
#pragma unroll
        for (int o = 4; o; o >>= 1) v += __shfl_xor_sync(0xFFu, v, o);
        if (threadIdx.x == 0) atomicAdd(out, v);
    }
}

// ---------------------------------------------------------------------------
extern "C" void kernel_launch(void* const* d_in, const int* in_sizes, int n_in,
                              void* d_out, int out_size) {
    (void)in_sizes; (void)n_in; (void)out_size;
    float* out = (float*)d_out;

    zero_kernel<<<(NLOSS * NN + 255) / 256, 256>>>(out);

    norm_kernel<<<(NHALF * BB) / 8, 256>>>(
        (const float*)d_in[0], (const float*)d_in[1], (const float*)d_in[2],
        (const float*)d_in[3], (const float*)d_in[4], (const float*)d_in[5]);

    dim3 grid(528, NLOSS);
    ctile_kernel<<<grid, 256>>>();

    ortho_kernel<<<(NORTHO * BB) / 8, 256>>>(out);
    finalize_kernel<<<(NLOSS * NN) / 8, 256>>>(out);
}

// round 3
// speedup vs baseline: 6.2123x; 6.2123x over previous
#include <cuda_runtime.h>
#include <cuda_bf16.h>
#include <math.h>
#include <stdint.h>

// Problem constants
#define BB 2048          // batch
#define NN 4096          // 2*B rows of z
#define DD 512           // half feature dim
#define NHALF 12         // 6 inputs x 2 halves
#define NLOSS 9          // contrastive losses
#define NORTHO 12        // ortho pairs
#define TINV 5.0f        // 1/temperature

// Scratch (device globals; no allocation allowed)
__device__ float         g_zn [NHALF * BB * DD];   // normalized halves (fp32)
__device__ __nv_bfloat16 g_zhi[NHALF * BB * DD];   // bf16 normalized
__device__ float         g_rowsum[NLOSS * NN];     // per-row sum of exp(sim/T)

__constant__ int c_cpA[NLOSS] = {0, 0, 2, 6, 6,  8, 1, 3, 5};
__constant__ int c_cpB[NLOSS] = {2, 4, 4, 8, 10, 10, 7, 9, 11};
__constant__ int c_opA[NORTHO] = {0, 2, 4, 1, 1, 3, 6, 8, 10, 7, 7, 9};
__constant__ int c_opB[NORTHO] = {1, 3, 5, 3, 5, 5, 7, 9, 11, 9, 11, 11};

// ---------------------------------------------------------------------------
__device__ __forceinline__ uint32_t smem_u32(const void* p) {
    uint32_t a;
    asm("{ .reg .u64 t; cvta.to.shared.u64 t, %1; cvt.u32.u64 %0, t; }" : "=r"(a) : "l"(p));
    return a;
}
__device__ __forceinline__ void cpasync16(uint32_t dst, const void* src) {
    asm volatile("cp.async.cg.shared.global [%0], [%1], 16;" :: "r"(dst), "l"(src));
}
__device__ __forceinline__ void ldsm4(uint32_t* r, uint32_t addr) {
    asm volatile("ldmatrix.sync.aligned.m8n8.x4.shared.b16 {%0,%1,%2,%3}, [%4];"
                 : "=r"(r[0]), "=r"(r[1]), "=r"(r[2]), "=r"(r[3]) : "r"(addr));
}
__device__ __forceinline__ void mma16816(float* d, const uint32_t* a,
                                         uint32_t b0, uint32_t b1) {
    asm volatile(
        "mma.sync.aligned.m16n8k16.row.col.f32.bf16.bf16.f32 "
        "{%0,%1,%2,%3}, {%4,%5,%6,%7}, {%8,%9}, {%0,%1,%2,%3};"
        : "+f"(d[0]), "+f"(d[1]), "+f"(d[2]), "+f"(d[3])
        : "r"(a[0]), "r"(a[1]), "r"(a[2]), "r"(a[3]), "r"(b0), "r"(b1));
}

// ---------------------------------------------------------------------------
// 0) zero rowsums + output scalar
// ---------------------------------------------------------------------------
__global__ void zero_kernel(float* out) {
    int i = blockIdx.x * blockDim.x + threadIdx.x;
    if (i < NLOSS * NN) g_rowsum[i] = 0.0f;
    if (i == 0) out[0] = 0.0f;
}

// ---------------------------------------------------------------------------
// 1) row-normalize all 12 halves; emit fp32 + bf16. One warp per row.
// ---------------------------------------------------------------------------
__global__ void norm_kernel(const float* __restrict__ i0, const float* __restrict__ i1,
                            const float* __restrict__ i2, const float* __restrict__ i3,
                            const float* __restrict__ i4, const float* __restrict__ i5) {
    int gw   = (blockIdx.x * blockDim.x + threadIdx.x) >> 5;
    int lane = threadIdx.x & 31;
    if (gw >= NHALF * BB) return;
    int h = gw / BB;
    int r = gw % BB;
    int m = h >> 1;
    const float* base = (m == 0) ? i0 : (m == 1) ? i1 : (m == 2) ? i2
                       : (m == 3) ? i3 : (m == 4) ? i4 : i5;
    const float* src = base + (size_t)r * 1024 + (size_t)(h & 1) * 512;

    float4 v[4];
    float ss = 0.0f;
#pragma unroll
    for (int w = 0; w < 4; w++) {
        v[w] = reinterpret_cast<const float4*>(src)[lane + w * 32];
        ss += v[w].x * v[w].x + v[w].y * v[w].y + v[w].z * v[w].z + v[w].w * v[w].w;
    }
#pragma unroll
    for (int o = 16; o; o >>= 1) ss += __shfl_xor_sync(0xFFFFFFFFu, ss, o);
    float inv = 1.0f / fmaxf(sqrtf(ss), 1e-8f);

    size_t rowoff = (size_t)h * BB * DD + (size_t)r * DD;
    float*          dst = g_zn + rowoff;
    __nv_bfloat162* dhi = reinterpret_cast<__nv_bfloat162*>(g_zhi + rowoff);
#pragma unroll
    for (int w = 0; w < 4; w++) {
        float4 o4;
        o4.x = v[w].x * inv; o4.y = v[w].y * inv;
        o4.z = v[w].z * inv; o4.w = v[w].w * inv;
        reinterpret_cast<float4*>(dst)[lane + w * 32] = o4;
        int pi = (lane + w * 32) * 2;
        dhi[pi]     = __floats2bfloat162_rn(o4.x, o4.y);
        dhi[pi + 1] = __floats2bfloat162_rn(o4.z, o4.w);
    }
}

// ---------------------------------------------------------------------------
// 2) bf16 HMMA tile kernel: 128x128 sim tile, exp epilogue.
//    Grid: x = 528 upper-triangle tiles, y = loss. 256 threads, 8 warps.
//    Warp tile 64x32 (wm = wid&1, wn = wid>>2... wn = wid>>1).
//    K chunks of 64 bf16, double-buffered cp.async, SW128 swizzle.
//    Dyn smem: 4 x 16KB buffers = 64KB.
// ---------------------------------------------------------------------------
#define KCHUNK 64
#define BUFSZ  16384          // 128 rows * 128 bytes
#define SWZOFF(row, seg) ((uint32_t)((row) * 128 + (((seg) ^ ((row) & 7)) << 4)))

__global__ __launch_bounds__(256, 1) void ctile_kernel() {
    extern __shared__ unsigned char smem[];
    const int loss = blockIdx.y;
    int t = blockIdx.x;
    int bi = 0;
    while (t >= 32 - bi) { t -= 32 - bi; bi++; }
    const int bj = bi + t;
    const int r0 = bi * 128, c0 = bj * 128;
    const bool diag = (bi == bj);
    const int tid = threadIdx.x, wid = tid >> 5, lane = tid & 31;
    const int wm = wid & 1, wn = wid >> 1;

    const __nv_bfloat16* ZA = g_zhi + (size_t)c_cpA[loss] * BB * DD;
    const __nv_bfloat16* ZB = g_zhi + (size_t)c_cpB[loss] * BB * DD;
    const __nv_bfloat16* sA = (r0 < BB) ? ZA + (size_t)r0 * DD : ZB + (size_t)(r0 - BB) * DD;
    const __nv_bfloat16* sB = (c0 < BB) ? ZA + (size_t)c0 * DD : ZB + (size_t)(c0 - BB) * DD;

    const uint32_t sbase = smem_u32(smem);

    float acc[4][4][4];
#pragma unroll
    for (int s = 0; s < 4; s++)
#pragma unroll
        for (int j = 0; j < 4; j++)
#pragma unroll
            for (int g = 0; g < 4; g++) acc[s][j][g] = 0.0f;

    // ---- prologue: prefetch chunk 0 into buffers 0 ----
    {
        const int kc = 0;
#pragma unroll
        for (int q = tid; q < 1024; q += 256) {
            int row = q >> 3, seg = q & 7;
            uint32_t off = SWZOFF(row, seg);
            cpasync16(sbase + off,             sA + (size_t)row * DD + kc + seg * 8);
            cpasync16(sbase + BUFSZ + off,     sB + (size_t)row * DD + kc + seg * 8);
        }
        asm volatile("cp.async.commit_group;" ::: "memory");
    }

    for (int c = 0; c < 8; c++) {
        if (c < 7) {
            const int kc = (c + 1) * KCHUNK;
            const uint32_t dbuf = sbase + ((c + 1) & 1) * (2 * BUFSZ);
#pragma unroll
            for (int q = tid; q < 1024; q += 256) {
                int row = q >> 3, seg = q & 7;
                uint32_t off = SWZOFF(row, seg);
                cpasync16(dbuf + off,         sA + (size_t)row * DD + kc + seg * 8);
                cpasync16(dbuf + BUFSZ + off, sB + (size_t)row * DD + kc + seg * 8);
            }
            asm volatile("cp.async.commit_group;" ::: "memory");
            asm volatile("cp.async.wait_group 1;" ::: "memory");
        } else {
            asm volatile("cp.async.wait_group 0;" ::: "memory");
        }
        __syncthreads();

        const uint32_t ab = sbase + (c & 1) * (2 * BUFSZ);
        const uint32_t bb = ab + BUFSZ;
#pragma unroll
        for (int kb = 0; kb < 4; kb++) {
            uint32_t af[4][4], bf[2][4];
#pragma unroll
            for (int s = 0; s < 4; s++) {
                int row = wm * 64 + s * 16 + (lane & 15);
                int seg = kb * 2 + (lane >> 4);
                ldsm4(af[s], ab + SWZOFF(row, seg));
            }
#pragma unroll
            for (int p = 0; p < 2; p++) {
                int row = wn * 32 + p * 16 + (lane & 7) + ((lane >> 4) << 3);
                int seg = kb * 2 + ((lane >> 3) & 1);
                ldsm4(bf[p], bb + SWZOFF(row, seg));
            }
#pragma unroll
            for (int s = 0; s < 4; s++)
#pragma unroll
                for (int j = 0; j < 4; j++)
                    mma16816(acc[s][j], af[s], bf[j >> 1][(j & 1) * 2],
                             bf[j >> 1][(j & 1) * 2 + 1]);
        }
        __syncthreads();
    }

    // --------------------------- epilogue ---------------------------
    const int rl  = lane >> 2;          // row within 8-group
    const int cl2 = (lane & 3) * 2;     // col pair base
    const int rbase = r0 + wm * 64;
    const int cbase = c0 + wn * 32;

#pragma unroll
    for (int s = 0; s < 4; s++)
#pragma unroll
        for (int j = 0; j < 4; j++)
#pragma unroll
            for (int g = 0; g < 4; g++) {
                int R = rbase + s * 16 + rl + ((g >> 1) << 3);
                int C = cbase + j * 8 + cl2 + (g & 1);
                float e = __expf(acc[s][j][g] * TINV);
                if (diag && R == C) e = 0.0f;
                acc[s][j][g] = e;
            }

    // row partials: rp[s*2+h] over this thread's 8 columns
    float rp[8];
#pragma unroll
    for (int i = 0; i < 8; i++) rp[i] = 0.0f;
#pragma unroll
    for (int s = 0; s < 4; s++)
#pragma unroll
        for (int j = 0; j < 4; j++) {
            rp[s * 2]     += acc[s][j][0] + acc[s][j][1];
            rp[s * 2 + 1] += acc[s][j][2] + acc[s][j][3];
        }
#pragma unroll
    for (int i = 0; i < 8; i++) {
        rp[i] += __shfl_xor_sync(0xFFFFFFFFu, rp[i], 1);
        rp[i] += __shfl_xor_sync(0xFFFFFFFFu, rp[i], 2);
    }

    // col partials: cp[j*2+b] over this thread's 8 rows
    float cp[8];
#pragma unroll
    for (int i = 0; i < 8; i++) cp[i] = 0.0f;
#pragma unroll
    for (int j = 0; j < 4; j++)
#pragma unroll
        for (int s = 0; s < 4; s++) {
            cp[j * 2]     += acc[s][j][0] + acc[s][j][2];
            cp[j * 2 + 1] += acc[s][j][1] + acc[s][j][3];
        }
#pragma unroll
    for (int i = 0; i < 8; i++) {
        cp[i] += __shfl_xor_sync(0xFFFFFFFFu, cp[i], 4);
        cp[i] += __shfl_xor_sync(0xFFFFFFFFu, cp[i], 8);
        cp[i] += __shfl_xor_sync(0xFFFFFFFFu, cp[i], 16);
    }

    float* rowred = reinterpret_cast<float*>(smem);      // [4][128]
    float* colred = rowred + 512;                        // [2][128]
    if ((lane & 3) == 0) {
#pragma unroll
        for (int s = 0; s < 4; s++)
#pragma unroll
            for (int h = 0; h < 2; h++)
                rowred[wn * 128 + wm * 64 + s * 16 + h * 8 + rl] = rp[s * 2 + h];
    }
    if (lane < 4) {
#pragma unroll
        for (int j = 0; j < 4; j++)
#pragma unroll
            for (int b = 0; b < 2; b++)
                colred[wm * 128 + wn * 32 + j * 8 + cl2 + b] = cp[j * 2 + b];
    }
    __syncthreads();

    if (tid < 128) {
        float rs = rowred[tid] + rowred[128 + tid] + rowred[256 + tid] + rowred[384 + tid];
        atomicAdd(&g_rowsum[loss * NN + r0 + tid], rs);
        if (!diag) {
            float cs = colred[tid] + colred[128 + tid];
            atomicAdd(&g_rowsum[loss * NN + c0 + tid], cs);
        }
    }
}

// ---------------------------------------------------------------------------
// 3) ortho losses (fp32 path, tiny)
// ---------------------------------------------------------------------------
__global__ void ortho_kernel(float* out) {
    int gw   = (blockIdx.x * blockDim.x + threadIdx.x) >> 5;
    int lane = threadIdx.x & 31;
    __shared__ float red[8];
    float c = 0.0f;
    if (gw < NORTHO * BB) {
        int p = gw / BB;
        int r = gw % BB;
        const float* a = g_zn + (size_t)c_opA[p] * BB * DD + (size_t)r * DD;
        const float* b = g_zn + (size_t)c_opB[p] * BB * DD + (size_t)r * DD;
        float d = 0.0f;
#pragma unroll
        for (int w = 0; w < 4; w++) {
            float4 x = reinterpret_cast<const float4*>(a)[lane + w * 32];
            float4 y = reinterpret_cast<const float4*>(b)[lane + w * 32];
            d += x.x * y.x + x.y * y.y + x.z * y.z + x.w * y.w;
        }
#pragma unroll
        for (int o = 16; o; o >>= 1) d += __shfl_xor_sync(0xFFFFFFFFu, d, o);
        if (lane == 0) c = (1.0f - d) * (1.0f / (float)BB);
    }
#pragma unroll
    for (int o = 16; o; o >>= 1) c += __shfl_xor_sync(0xFFFFFFFFu, c, o);
    if (lane == 0) red[threadIdx.x >> 5] = c;
    __syncthreads();
    if (threadIdx.x < 8) {
        float v = red[threadIdx.x];
#pragma unroll
        for (int o = 4; o; o >>= 1) v += __shfl_xor_sync(0xFFu, v, o);
        if (threadIdx.x == 0) atomicAdd(out, v);
    }
}

// ---------------------------------------------------------------------------
// 4) finalize contrastive: log(rowsum) minus exact fp32 pos dot
// ---------------------------------------------------------------------------
__global__ void finalize_kernel(float* out) {
    int gw   = (blockIdx.x * blockDim.x + threadIdx.x) >> 5;
    int lane = threadIdx.x & 31;
    __shared__ float red[8];
    float c = 0.0f;
    if (gw < NLOSS * NN) {
        int loss = gw / NN;
        int i    = gw % NN;
        float val = logf(g_rowsum[loss * NN + i]);
        if (i < BB) {
            const float* a = g_zn + (size_t)c_cpA[loss] * BB * DD + (size_t)i * DD;
            const float* b = g_zn + (size_t)c_cpB[loss] * BB * DD + (size_t)i * DD;
            float d = 0.0f;
#pragma unroll
            for (int w = 0; w < 4; w++) {
                float4 x = reinterpret_cast<const float4*>(a)[lane + w * 32];
                float4 y = reinterpret_cast<const float4*>(b)[lane + w * 32];
                d += x.x * y.x + x.y * y.y + x.z * y.z + x.w * y.w;
            }
#pragma unroll
            for (int o = 16; o; o >>= 1) d += __shfl_xor_sync(0xFFFFFFFFu, d, o);
            val -= 2.0f * d * TINV;   // pos_i == pos_{i+B}
        }
        if (lane == 0) c = val * (1.0f / (float)NN);
    }
#pragma unroll
    for (int o = 16; o; o >>= 1) c += __shfl_xor_sync(0xFFFFFFFFu, c, o);
    if (lane == 0) red[threadIdx.x >> 5] = c;
    __syncthreads();
    if (threadIdx.x < 8) {
        float v = red[threadIdx.x];
#pragma unroll
        for (int o = 4; o; o >>= 1) v += __shfl_xor_sync(0xFFu, v, o);
        if (threadIdx.x == 0) atomicAdd(out, v);
    }
}

// ---------------------------------------------------------------------------
extern "C" void kernel_launch(void* const* d_in, const int* in_sizes, int n_in,
                              void* d_out, int out_size) {
    (void)in_sizes; (void)n_in; (void)out_size;
    float* out = (float*)d_out;

    cudaFuncSetAttribute(ctile_kernel, cudaFuncAttributeMaxDynamicSharedMemorySize,
                         4 * BUFSZ);

    zero_kernel<<<(NLOSS * NN + 255) / 256, 256>>>(out);

    norm_kernel<<<(NHALF * BB) / 8, 256>>>(
        (const float*)d_in[0], (const float*)d_in[1], (const float*)d_in[2],
        (const float*)d_in[3], (const float*)d_in[4], (const float*)d_in[5]);

    dim3 grid(528, NLOSS);
    ctile_kernel<<<grid, 256, 4 * BUFSZ>>>();

    ortho_kernel<<<(NORTHO * BB) / 8, 256>>>(out);
    finalize_kernel<<<(NLOSS * NN) / 8, 256>>>(out);
}

// round 4
// speedup vs baseline: 8.0080x; 1.2891x over previous
#include <cuda_runtime.h>
#include <cuda_bf16.h>
#include <cuda_fp16.h>
#include <math.h>
#include <stdint.h>

// Problem constants
#define BB 2048          // batch
#define NN 4096          // 2*B rows of z
#define DD 512           // half feature dim
#define NHALF 12         // 6 inputs x 2 halves
#define NLOSS 9          // contrastive losses
#define NORTHO 12        // ortho pairs
#define TINV 5.0f        // 1/temperature
// sqrt(TINV * log2(e)) folded into bf16 operands => acc = sim*TINV*log2e
#define SCALE_K 2.6857913787767947f

// Scratch (device globals; no allocation allowed)
__device__ float         g_zn [NHALF * BB * DD];   // normalized halves (fp32, unscaled)
__device__ __nv_bfloat16 g_zhi[NHALF * BB * DD];   // bf16 normalized * SCALE_K
__device__ float         g_rowsum[NLOSS * NN];     // per-row sum of exp(sim/T)

__constant__ int c_cpA[NLOSS] = {0, 0, 2, 6, 6,  8, 1, 3, 5};
__constant__ int c_cpB[NLOSS] = {2, 4, 4, 8, 10, 10, 7, 9, 11};
__constant__ int c_opA[NORTHO] = {0, 2, 4, 1, 1, 3, 6, 8, 10, 7, 7, 9};
__constant__ int c_opB[NORTHO] = {1, 3, 5, 3, 5, 5, 7, 9, 11, 9, 11, 11};

// ---------------------------------------------------------------------------
__device__ __forceinline__ uint32_t smem_u32(const void* p) {
    uint32_t a;
    asm("{ .reg .u64 t; cvta.to.shared.u64 t, %1; cvt.u32.u64 %0, t; }" : "=r"(a) : "l"(p));
    return a;
}
__device__ __forceinline__ void cpasync16(uint32_t dst, const void* src) {
    asm volatile("cp.async.cg.shared.global [%0], [%1], 16;" :: "r"(dst), "l"(src));
}
__device__ __forceinline__ void ldsm4(uint32_t* r, uint32_t addr) {
    asm volatile("ldmatrix.sync.aligned.m8n8.x4.shared.b16 {%0,%1,%2,%3}, [%4];"
                 : "=r"(r[0]), "=r"(r[1]), "=r"(r[2]), "=r"(r[3]) : "r"(addr));
}
__device__ __forceinline__ void mma16816(float* d, const uint32_t* a,
                                         uint32_t b0, uint32_t b1) {
    asm volatile(
        "mma.sync.aligned.m16n8k16.row.col.f32.bf16.bf16.f32 "
        "{%0,%1,%2,%3}, {%4,%5,%6,%7}, {%8,%9}, {%0,%1,%2,%3};"
        : "+f"(d[0]), "+f"(d[1]), "+f"(d[2]), "+f"(d[3])
        : "r"(a[0]), "r"(a[1]), "r"(a[2]), "r"(a[3]), "r"(b0), "r"(b1));
}
__device__ __forceinline__ float ex2f(float x) {
    float r;
    asm("ex2.approx.f32 %0, %1;" : "=f"(r) : "f"(x));
    return r;
}

// ---------------------------------------------------------------------------
// 0) zero rowsums + output scalar
// ---------------------------------------------------------------------------
__global__ void zero_kernel(float* out) {
    int i = blockIdx.x * blockDim.x + threadIdx.x;
    if (i < NLOSS * NN) g_rowsum[i] = 0.0f;
    if (i == 0) out[0] = 0.0f;
}

// ---------------------------------------------------------------------------
// 1) row-normalize all 12 halves; emit fp32 + scaled bf16. One warp per row.
// ---------------------------------------------------------------------------
__global__ void norm_kernel(const float* __restrict__ i0, const float* __restrict__ i1,
                            const float* __restrict__ i2, const float* __restrict__ i3,
                            const float* __restrict__ i4, const float* __restrict__ i5) {
    int gw   = (blockIdx.x * blockDim.x + threadIdx.x) >> 5;
    int lane = threadIdx.x & 31;
    if (gw >= NHALF * BB) return;
    int h = gw / BB;
    int r = gw % BB;
    int m = h >> 1;
    const float* base = (m == 0) ? i0 : (m == 1) ? i1 : (m == 2) ? i2
                       : (m == 3) ? i3 : (m == 4) ? i4 : i5;
    const float* src = base + (size_t)r * 1024 + (size_t)(h & 1) * 512;

    float4 v[4];
    float ss = 0.0f;
#pragma unroll
    for (int w = 0; w < 4; w++) {
        v[w] = reinterpret_cast<const float4*>(src)[lane + w * 32];
        ss += v[w].x * v[w].x + v[w].y * v[w].y + v[w].z * v[w].z + v[w].w * v[w].w;
    }
#pragma unroll
    for (int o = 16; o; o >>= 1) ss += __shfl_xor_sync(0xFFFFFFFFu, ss, o);
    float inv = 1.0f / fmaxf(sqrtf(ss), 1e-8f);
    float invk = inv * SCALE_K;

    size_t rowoff = (size_t)h * BB * DD + (size_t)r * DD;
    float*          dst = g_zn + rowoff;
    __nv_bfloat162* dhi = reinterpret_cast<__nv_bfloat162*>(g_zhi + rowoff);
#pragma unroll
    for (int w = 0; w < 4; w++) {
        float4 o4;
        o4.x = v[w].x * inv; o4.y = v[w].y * inv;
        o4.z = v[w].z * inv; o4.w = v[w].w * inv;
        reinterpret_cast<float4*>(dst)[lane + w * 32] = o4;
        int pi = (lane + w * 32) * 2;
        dhi[pi]     = __floats2bfloat162_rn(v[w].x * invk, v[w].y * invk);
        dhi[pi + 1] = __floats2bfloat162_rn(v[w].z * invk, v[w].w * invk);
    }
}

// ---------------------------------------------------------------------------
// 2) bf16 HMMA tile kernel: 128x128 sim tile, ex2 epilogue (acc pre-scaled).
//    Grid: x = 528 upper-triangle tiles, y = loss. 256 threads, 8 warps.
//    K chunks of 64 bf16, double-buffered cp.async, XOR swizzle.
//    Dyn smem 64KB; 2 CTAs/SM for mainloop/epilogue overlap.
// ---------------------------------------------------------------------------
#define KCHUNK 64
#define BUFSZ  16384          // 128 rows * 128 bytes
#define SWZOFF(row, seg) ((uint32_t)((row) * 128 + (((seg) ^ ((row) & 7)) << 4)))

__global__ __launch_bounds__(256, 2) void ctile_kernel() {
    extern __shared__ unsigned char smem[];
    const int loss = blockIdx.y;
    int t = blockIdx.x;
    int bi = 0;
    while (t >= 32 - bi) { t -= 32 - bi; bi++; }
    const int bj = bi + t;
    const int r0 = bi * 128, c0 = bj * 128;
    const bool diag = (bi == bj);
    const int tid = threadIdx.x, wid = tid >> 5, lane = tid & 31;
    const int wm = wid & 1, wn = wid >> 1;

    const __nv_bfloat16* ZA = g_zhi + (size_t)c_cpA[loss] * BB * DD;
    const __nv_bfloat16* ZB = g_zhi + (size_t)c_cpB[loss] * BB * DD;
    const __nv_bfloat16* sA = (r0 < BB) ? ZA + (size_t)r0 * DD : ZB + (size_t)(r0 - BB) * DD;
    const __nv_bfloat16* sB = (c0 < BB) ? ZA + (size_t)c0 * DD : ZB + (size_t)(c0 - BB) * DD;

    const uint32_t sbase = smem_u32(smem);

    float acc[4][4][4];
#pragma unroll
    for (int s = 0; s < 4; s++)
#pragma unroll
        for (int j = 0; j < 4; j++)
#pragma unroll
            for (int g = 0; g < 4; g++) acc[s][j][g] = 0.0f;

    // ---- prologue: prefetch chunk 0 ----
    {
#pragma unroll
        for (int q = tid; q < 1024; q += 256) {
            int row = q >> 3, seg = q & 7;
            uint32_t off = SWZOFF(row, seg);
            cpasync16(sbase + off,         sA + (size_t)row * DD + seg * 8);
            cpasync16(sbase + BUFSZ + off, sB + (size_t)row * DD + seg * 8);
        }
        asm volatile("cp.async.commit_group;" ::: "memory");
    }

    for (int c = 0; c < 8; c++) {
        if (c < 7) {
            const int kc = (c + 1) * KCHUNK;
            const uint32_t dbuf = sbase + ((c + 1) & 1) * (2 * BUFSZ);
#pragma unroll
            for (int q = tid; q < 1024; q += 256) {
                int row = q >> 3, seg = q & 7;
                uint32_t off = SWZOFF(row, seg);
                cpasync16(dbuf + off,         sA + (size_t)row * DD + kc + seg * 8);
                cpasync16(dbuf + BUFSZ + off, sB + (size_t)row * DD + kc + seg * 8);
            }
            asm volatile("cp.async.commit_group;" ::: "memory");
            asm volatile("cp.async.wait_group 1;" ::: "memory");
        } else {
            asm volatile("cp.async.wait_group 0;" ::: "memory");
        }
        __syncthreads();

        const uint32_t ab = sbase + (c & 1) * (2 * BUFSZ);
        const uint32_t bb = ab + BUFSZ;
#pragma unroll
        for (int kb = 0; kb < 4; kb++) {
            uint32_t af[4][4], bf[2][4];
#pragma unroll
            for (int s = 0; s < 4; s++) {
                int row = wm * 64 + s * 16 + (lane & 15);
                int seg = kb * 2 + (lane >> 4);
                ldsm4(af[s], ab + SWZOFF(row, seg));
            }
#pragma unroll
            for (int p = 0; p < 2; p++) {
                int row = wn * 32 + p * 16 + (lane & 7) + ((lane >> 4) << 3);
                int seg = kb * 2 + ((lane >> 3) & 1);
                ldsm4(bf[p], bb + SWZOFF(row, seg));
            }
#pragma unroll
            for (int s = 0; s < 4; s++)
#pragma unroll
                for (int j = 0; j < 4; j++)
                    mma16816(acc[s][j], af[s], bf[j >> 1][(j & 1) * 2],
                             bf[j >> 1][(j & 1) * 2 + 1]);
        }
        __syncthreads();
    }

    // --------------------------- epilogue ---------------------------
    // acc already == sim * TINV * log2(e); exp(sim/T) = ex2(acc)
    const int rl  = lane >> 2;          // row within 8-group
    const int cl2 = (lane & 3) * 2;     // col pair base

    float rp[8], cp[8];

    if (!diag) {
        // fast path: f16x2 ex2, half2 partial sums
        __half2 rs01[4], rs23[4], csm[4];
#pragma unroll
        for (int i = 0; i < 4; i++) {
            rs01[i] = __float2half2_rn(0.0f);
            rs23[i] = __float2half2_rn(0.0f);
            csm[i]  = __float2half2_rn(0.0f);
        }
#pragma unroll
        for (int s = 0; s < 4; s++)
#pragma unroll
            for (int j = 0; j < 4; j++) {
                __half2 e01 = h2exp2(__floats2half2_rn(acc[s][j][0], acc[s][j][1]));
                __half2 e23 = h2exp2(__floats2half2_rn(acc[s][j][2], acc[s][j][3]));
                rs01[s] = __hadd2(rs01[s], e01);
                rs23[s] = __hadd2(rs23[s], e23);
                csm[j]  = __hadd2(csm[j], __hadd2(e01, e23));
            }
#pragma unroll
        for (int s = 0; s < 4; s++) {
            rp[s * 2]     = __low2float(rs01[s]) + __high2float(rs01[s]);
            rp[s * 2 + 1] = __low2float(rs23[s]) + __high2float(rs23[s]);
        }
#pragma unroll
        for (int j = 0; j < 4; j++) {
            cp[j * 2]     = __low2float(csm[j]);
            cp[j * 2 + 1] = __high2float(csm[j]);
        }
    } else {
        // diag path: scalar ex2 with self-masking
        const int rbase = r0 + wm * 64;
        const int cbase = c0 + wn * 32;
#pragma unroll
        for (int s = 0; s < 4; s++)
#pragma unroll
            for (int j = 0; j < 4; j++)
#pragma unroll
                for (int g = 0; g < 4; g++) {
                    int R = rbase + s * 16 + rl + ((g >> 1) << 3);
                    int C = cbase + j * 8 + cl2 + (g & 1);
                    float e = ex2f(acc[s][j][g]);
                    if (R == C) e = 0.0f;
                    acc[s][j][g] = e;
                }
#pragma unroll
        for (int i = 0; i < 8; i++) { rp[i] = 0.0f; cp[i] = 0.0f; }
#pragma unroll
        for (int s = 0; s < 4; s++)
#pragma unroll
            for (int j = 0; j < 4; j++) {
                rp[s * 2]     += acc[s][j][0] + acc[s][j][1];
                rp[s * 2 + 1] += acc[s][j][2] + acc[s][j][3];
                cp[j * 2]     += acc[s][j][0] + acc[s][j][2];
                cp[j * 2 + 1] += acc[s][j][1] + acc[s][j][3];
            }
    }

#pragma unroll
    for (int i = 0; i < 8; i++) {
        rp[i] += __shfl_xor_sync(0xFFFFFFFFu, rp[i], 1);
        rp[i] += __shfl_xor_sync(0xFFFFFFFFu, rp[i], 2);
    }
#pragma unroll
    for (int i = 0; i < 8; i++) {
        cp[i] += __shfl_xor_sync(0xFFFFFFFFu, cp[i], 4);
        cp[i] += __shfl_xor_sync(0xFFFFFFFFu, cp[i], 8);
        cp[i] += __shfl_xor_sync(0xFFFFFFFFu, cp[i], 16);
    }

    float* rowred = reinterpret_cast<float*>(smem);      // [4][128]
    float* colred = rowred + 512;                        // [2][128]
    if ((lane & 3) == 0) {
#pragma unroll
        for (int s = 0; s < 4; s++)
#pragma unroll
            for (int h = 0; h < 2; h++)
                rowred[wn * 128 + wm * 64 + s * 16 + h * 8 + rl] = rp[s * 2 + h];
    }
    if (lane < 4) {
#pragma unroll
        for (int j = 0; j < 4; j++)
#pragma unroll
            for (int b = 0; b < 2; b++)
                colred[wm * 128 + wn * 32 + j * 8 + cl2 + b] = cp[j * 2 + b];
    }
    __syncthreads();

    if (tid < 128) {
        float rs = rowred[tid] + rowred[128 + tid] + rowred[256 + tid] + rowred[384 + tid];
        atomicAdd(&g_rowsum[loss * NN + r0 + tid], rs);
        if (!diag) {
            float cs = colred[tid] + colred[128 + tid];
            atomicAdd(&g_rowsum[loss * NN + c0 + tid], cs);
        }
    }
}

// ---------------------------------------------------------------------------
// 3) ortho losses (fp32 path, tiny)
// ---------------------------------------------------------------------------
__global__ void ortho_kernel(float* out) {
    int gw   = (blockIdx.x * blockDim.x + threadIdx.x) >> 5;
    int lane = threadIdx.x & 31;
    __shared__ float red[8];
    float c = 0.0f;
    if (gw < NORTHO * BB) {
        int p = gw / BB;
        int r = gw % BB;
        const float* a = g_zn + (size_t)c_opA[p] * BB * DD + (size_t)r * DD;
        const float* b = g_zn + (size_t)c_opB[p] * BB * DD + (size_t)r * DD;
        float d = 0.0f;
#pragma unroll
        for (int w = 0; w < 4; w++) {
            float4 x = reinterpret_cast<const float4*>(a)[lane + w * 32];
            float4 y = reinterpret_cast<const float4*>(b)[lane + w * 32];
            d += x.x * y.x + x.y * y.y + x.z * y.z + x.w * y.w;
        }
#pragma unroll
        for (int o = 16; o; o >>= 1) d += __shfl_xor_sync(0xFFFFFFFFu, d, o);
        if (lane == 0) c = (1.0f - d) * (1.0f / (float)BB);
    }
#pragma unroll
    for (int o = 16; o; o >>= 1) c += __shfl_xor_sync(0xFFFFFFFFu, c, o);
    if (lane == 0) red[threadIdx.x >> 5] = c;
    __syncthreads();
    if (threadIdx.x < 8) {
        float v = red[threadIdx.x];
#pragma unroll
        for (int o = 4; o; o >>= 1) v += __shfl_xor_sync(0xFFu, v, o);
        if (threadIdx.x == 0) atomicAdd(out, v);
    }
}

// ---------------------------------------------------------------------------
// 4) finalize contrastive: log(rowsum) minus exact fp32 pos dot
// ---------------------------------------------------------------------------
__global__ void finalize_kernel(float* out) {
    int gw   = (blockIdx.x * blockDim.x + threadIdx.x) >> 5;
    int lane = threadIdx.x & 31;
    __shared__ float red[8];
    float c = 0.0f;
    if (gw < NLOSS * NN) {
        int loss = gw / NN;
        int i    = gw % NN;
        float val = logf(g_rowsum[loss * NN + i]);
        if (i < BB) {
            const float* a = g_zn + (size_t)c_cpA[loss] * BB * DD + (size_t)i * DD;
            const float* b = g_zn + (size_t)c_cpB[loss] * BB * DD + (size_t)i * DD;
            float d = 0.0f;
#pragma unroll
            for (int w = 0; w < 4; w++) {
                float4 x = reinterpret_cast<const float4*>(a)[lane + w * 32];
                float4 y = reinterpret_cast<const float4*>(b)[lane + w * 32];
                d += x.x * y.x + x.y * y.y + x.z * y.z + x.w * y.w;
            }
#pragma unroll
            for (int o = 16; o; o >>= 1) d += __shfl_xor_sync(0xFFFFFFFFu, d, o);
            val -= 2.0f * d * TINV;   // pos_i == pos_{i+B}
        }
        if (lane == 0) c = val * (1.0f / (float)NN);
    }
#pragma unroll
    for (int o = 16; o; o >>= 1) c += __shfl_xor_sync(0xFFFFFFFFu, c, o);
    if (lane == 0) red[threadIdx.x >> 5] = c;
    __syncthreads();
    if (threadIdx.x < 8) {
        float v = red[threadIdx.x];
#pragma unroll
        for (int o = 4; o; o >>= 1) v += __shfl_xor_sync(0xFFu, v, o);
        if (threadIdx.x == 0) atomicAdd(out, v);
    }
}

// ---------------------------------------------------------------------------
extern "C" void kernel_launch(void* const* d_in, const int* in_sizes, int n_in,
                              void* d_out, int out_size) {
    (void)in_sizes; (void)n_in; (void)out_size;
    float* out = (float*)d_out;

    cudaFuncSetAttribute(ctile_kernel, cudaFuncAttributeMaxDynamicSharedMemorySize,
                         4 * BUFSZ);

    zero_kernel<<<(NLOSS * NN + 255) / 256, 256>>>(out);

    norm_kernel<<<(NHALF * BB) / 8, 256>>>(
        (const float*)d_in[0], (const float*)d_in[1], (const float*)d_in[2],
        (const float*)d_in[3], (const float*)d_in[4], (const float*)d_in[5]);

    dim3 grid(528, NLOSS);
    ctile_kernel<<<grid, 256, 4 * BUFSZ>>>();

    ortho_kernel<<<(NORTHO * BB) / 8, 256>>>(out);
    finalize_kernel<<<(NLOSS * NN) / 8, 256>>>(out);
}